// round 2
// baseline (speedup 1.0000x reference)
#include <cuda_runtime.h>
#include <math.h>

#define NG 1024
#define NV 2
#define HW 128
#define SH_C0 0.28209479177387814f
#define SH_C1 0.4886025119029199f

// Scratch (allocation-free): unsorted + sorted per-gaussian data per view.
// A = (u, v, conic_a, conic_b); B = (conic_c, opacity, colR, colG); b = colB
__device__ float4 d_uA[NV][NG], d_uB[NV][NG];
__device__ float  d_ub[NV][NG];
__device__ unsigned long long d_uM[NV][NG];
__device__ float4 d_sA[NV][NG], d_sB[NV][NG];
__device__ float  d_sb[NV][NG];
__device__ unsigned long long d_sM[NV][NG];

__global__ __launch_bounds__(NG, 1)
void prep_kernel(const float* __restrict__ xyz,
                 const float* __restrict__ feats,
                 const float* __restrict__ scal,
                 const float* __restrict__ rot,
                 const float* __restrict__ opac,
                 const float* __restrict__ C2W,
                 const float* __restrict__ intr)
{
    const int v = blockIdx.x;
    const int i = threadIdx.x;

    // ---- camera (rigid c2w -> w2c by transpose) ----
    const float* M = C2W + v * 16;
    const float Rc00 = M[0], Rc01 = M[4], Rc02 = M[8];
    const float Rc10 = M[1], Rc11 = M[5], Rc12 = M[9];
    const float Rc20 = M[2], Rc21 = M[6], Rc22 = M[10];
    const float cam0 = M[3], cam1 = M[7], cam2 = M[11];
    const float tc0 = -(Rc00 * cam0 + Rc01 * cam1 + Rc02 * cam2);
    const float tc1 = -(Rc10 * cam0 + Rc11 * cam1 + Rc12 * cam2);
    const float tc2 = -(Rc20 * cam0 + Rc21 * cam1 + Rc22 * cam2);
    const float fx = intr[v * 4 + 0], fy = intr[v * 4 + 1];
    const float cx = intr[v * 4 + 2], cy = intr[v * 4 + 3];

    // ---- gaussian ----
    const float X = xyz[i * 3 + 0], Y = xyz[i * 3 + 1], Z = xyz[i * 3 + 2];
    float qw = rot[i * 4 + 0], qx = rot[i * 4 + 1], qy = rot[i * 4 + 2], qz = rot[i * 4 + 3];
    {
        float qn = sqrtf(qw * qw + qx * qx + qy * qy + qz * qz);
        float inv = 1.0f / qn;
        qw *= inv; qx *= inv; qy *= inv; qz *= inv;
    }
    const float r00 = 1.f - 2.f * (qy * qy + qz * qz);
    const float r01 = 2.f * (qx * qy - qw * qz);
    const float r02 = 2.f * (qx * qz + qw * qy);
    const float r10 = 2.f * (qx * qy + qw * qz);
    const float r11 = 1.f - 2.f * (qx * qx + qz * qz);
    const float r12 = 2.f * (qy * qz - qw * qx);
    const float r20 = 2.f * (qx * qz - qw * qy);
    const float r21 = 2.f * (qy * qz + qw * qx);
    const float r22 = 1.f - 2.f * (qx * qx + qy * qy);
    const float s0 = scal[i * 3 + 0], s1 = scal[i * 3 + 1], s2 = scal[i * 3 + 2];
    const float m00 = r00 * s0, m01 = r01 * s1, m02 = r02 * s2;
    const float m10 = r10 * s0, m11 = r11 * s1, m12 = r12 * s2;
    const float m20 = r20 * s0, m21 = r21 * s1, m22 = r22 * s2;
    // cov3d = M M^T (symmetric)
    const float S00 = m00 * m00 + m01 * m01 + m02 * m02;
    const float S01 = m00 * m10 + m01 * m11 + m02 * m12;
    const float S02 = m00 * m20 + m01 * m21 + m02 * m22;
    const float S11 = m10 * m10 + m11 * m11 + m12 * m12;
    const float S12 = m10 * m20 + m11 * m21 + m12 * m22;
    const float S22 = m20 * m20 + m21 * m21 + m22 * m22;

    // camera-space position
    const float px = Rc00 * X + Rc01 * Y + Rc02 * Z + tc0;
    const float py = Rc10 * X + Rc11 * Y + Rc12 * Z + tc1;
    const float pz = Rc20 * X + Rc21 * Y + Rc22 * Z + tc2;
    const bool valid = pz > 0.2f;
    const float zs = fmaxf(pz, 0.2f);
    const float u  = fx * px / zs + cx;
    const float vv = fy * py / zs + cy;

    // T = J * Rcw (2x3)
    const float j00 = fx / zs;
    const float j02 = -fx * px / (zs * zs);
    const float j11 = fy / zs;
    const float j12 = -fy * py / (zs * zs);
    const float T00 = j00 * Rc00 + j02 * Rc20;
    const float T01 = j00 * Rc01 + j02 * Rc21;
    const float T02 = j00 * Rc02 + j02 * Rc22;
    const float T10 = j11 * Rc10 + j12 * Rc20;
    const float T11 = j11 * Rc11 + j12 * Rc21;
    const float T12 = j11 * Rc12 + j12 * Rc22;
    // cov2d = T Sigma T^T
    const float w0 = S00 * T00 + S01 * T01 + S02 * T02;
    const float w1 = S01 * T00 + S11 * T01 + S12 * T02;
    const float w2 = S02 * T00 + S12 * T01 + S22 * T02;
    const float a = T00 * w0 + T01 * w1 + T02 * w2 + 0.3f;
    const float b = T10 * w0 + T11 * w1 + T12 * w2;
    const float x0 = S00 * T10 + S01 * T11 + S02 * T12;
    const float x1 = S01 * T10 + S11 * T11 + S12 * T12;
    const float x2 = S02 * T10 + S12 * T11 + S22 * T12;
    const float c = T10 * x0 + T11 * x1 + T12 * x2 + 0.3f;
    const float det = fmaxf(a * c - b * b, 1e-6f);
    const float invd = 1.0f / det;
    const float ca = c * invd, cbv = -b * invd, cc = a * invd;

    // SH color (degree 1)
    float ddx = X - cam0, ddy = Y - cam1, ddz = Z - cam2;
    {
        float n = sqrtf(ddx * ddx + ddy * ddy + ddz * ddz);
        float inv = 1.0f / n;
        ddx *= inv; ddy *= inv; ddz *= inv;
    }
    float col[3];
    #pragma unroll
    for (int ch = 0; ch < 3; ++ch) {
        float f0 = feats[(i * 4 + 0) * 3 + ch];
        float f1 = feats[(i * 4 + 1) * 3 + ch];
        float f2 = feats[(i * 4 + 2) * 3 + ch];
        float f3 = feats[(i * 4 + 3) * 3 + ch];
        float cv = SH_C0 * f0 - SH_C1 * ddy * f1 + SH_C1 * ddz * f2 - SH_C1 * ddx * f3 + 0.5f;
        col[ch] = fmaxf(cv, 0.0f);
    }
    const float opv = valid ? opac[i] : 0.0f;
    const float key = valid ? pz : __int_as_float(0x7f800000);

    // tile coverage mask (8x8 tiles of 16x16 px)
    unsigned long long mask = 0ull;
    if (opv >= (1.0f / 255.0f)) {
        float tau = logf(255.0f * opv);                 // >= 0
        float rx = sqrtf(fmaxf(2.0f * tau * a, 0.0f)) + 1.0f;
        float ry = sqrtf(fmaxf(2.0f * tau * c, 0.0f)) + 1.0f;
        int tx0 = (int)fmaxf(fminf(floorf((u  - rx) * 0.0625f), 9.0f),  0.0f);
        int tx1 = (int)fmaxf(fminf(floorf((u  + rx) * 0.0625f), 7.0f), -1.0f);
        int ty0 = (int)fmaxf(fminf(floorf((vv - ry) * 0.0625f), 9.0f),  0.0f);
        int ty1 = (int)fmaxf(fminf(floorf((vv + ry) * 0.0625f), 7.0f), -1.0f);
        if (tx0 <= tx1 && ty0 <= ty1) {
            unsigned int row = (0xFFu << tx0) & (0xFFu >> (7 - tx1));
            for (int ty = ty0; ty <= ty1; ++ty)
                mask |= ((unsigned long long)row) << (8 * ty);
        }
    }

    d_uA[v][i] = make_float4(u, vv, ca, cbv);
    d_uB[v][i] = make_float4(cc, opv, col[0], col[1]);
    d_ub[v][i] = col[2];
    d_uM[v][i] = mask;

    // ---- bitonic sort by depth (ascending), payload = original index ----
    __shared__ float s_key[NG];
    __shared__ int   s_val[NG];
    s_key[i] = key;
    s_val[i] = i;
    for (int k = 2; k <= NG; k <<= 1) {
        for (int j = k >> 1; j > 0; j >>= 1) {
            __syncthreads();
            int ixj = i ^ j;
            if (ixj > i) {
                float ki = s_key[i], kj = s_key[ixj];
                bool up = ((i & k) == 0);
                bool sw = up ? (ki > kj) : (ki < kj);
                if (sw) {
                    s_key[i] = kj; s_key[ixj] = ki;
                    int t = s_val[i]; s_val[i] = s_val[ixj]; s_val[ixj] = t;
                }
            }
        }
    }
    __syncthreads();

    const int src = s_val[i];
    d_sA[v][i] = d_uA[v][src];
    d_sB[v][i] = d_uB[v][src];
    d_sb[v][i] = d_ub[v][src];
    d_sM[v][i] = d_uM[v][src];
}

__global__ __launch_bounds__(256)
void render_kernel(float* __restrict__ out)
{
    __shared__ int    s_list[NG];
    __shared__ float4 sA[NG];
    __shared__ float4 sB[NG];
    __shared__ float  sCb[NG];
    __shared__ int    s_cnt;

    const int v    = blockIdx.y;
    const int tile = blockIdx.x;           // 0..63 -> (tile&7, tile>>3)
    const int tid  = threadIdx.x;

    // warp 0: ordered compaction of gaussians overlapping this tile
    if (tid < 32) {
        int cnt = 0;
        for (int base = 0; base < NG; base += 32) {
            unsigned long long m = d_sM[v][base + tid];
            bool hit = (m >> tile) & 1ull;
            unsigned int bal = __ballot_sync(0xffffffffu, hit);
            if (hit) {
                int pos = cnt + __popc(bal & ((1u << tid) - 1u));
                s_list[pos] = base + tid;
            }
            cnt += __popc(bal);
        }
        if (tid == 0) s_cnt = cnt;
    }
    __syncthreads();
    const int cnt = s_cnt;

    for (int i = tid; i < cnt; i += 256) {
        int j = s_list[i];
        sA[i]  = d_sA[v][j];
        sB[i]  = d_sB[v][j];
        sCb[i] = d_sb[v][j];
    }
    __syncthreads();

    const int pxi = (tile & 7) * 16 + (tid & 15);
    const int pyi = (tile >> 3) * 16 + (tid >> 4);
    const float gx = pxi + 0.5f;
    const float gy = pyi + 0.5f;

    float T = 1.0f, cr = 0.0f, cg = 0.0f, cb = 0.0f;
    for (int i = 0; i < cnt; ++i) {
        float4 A = sA[i];
        float4 B = sB[i];
        float dx = gx - A.x;
        float dy = gy - A.y;
        float pwr = -0.5f * (A.z * dx * dx + B.x * dy * dy) - A.w * dx * dy;
        float al = B.y * __expf(pwr);
        al = fminf(al, 0.99f);
        if (pwr > 0.0f || al < (1.0f / 255.0f)) al = 0.0f;
        float w = al * T;
        cr = fmaf(w, B.z, cr);
        cg = fmaf(w, B.w, cg);
        cb = fmaf(w, sCb[i], cb);
        T *= (1.0f - al);
        if (__all_sync(0xffffffffu, T < 1e-5f)) break;
    }

    const int o = ((v * 3) * HW + pyi) * HW + pxi;
    out[o]            = cr;
    out[o + HW * HW]  = cg;
    out[o + 2 * HW * HW] = cb;
}

extern "C" void kernel_launch(void* const* d_in, const int* in_sizes, int n_in,
                              void* d_out, int out_size)
{
    const float* xyz   = (const float*)d_in[0];
    const float* feats = (const float*)d_in[1];
    const float* scal  = (const float*)d_in[2];
    const float* rot   = (const float*)d_in[3];
    const float* opac  = (const float*)d_in[4];

    // locate C2W (32 elems) and intrinsics (8 elems) robustly (height/width
    // scalars may or may not occupy slots 5/6)
    const float* C2W  = nullptr;
    const float* intr = nullptr;
    for (int k = 5; k < n_in; ++k) {
        if (in_sizes[k] == 32 && !C2W)  C2W  = (const float*)d_in[k];
        else if (in_sizes[k] == 8 && !intr) intr = (const float*)d_in[k];
    }
    if (!C2W)  C2W  = (const float*)d_in[n_in - 2];
    if (!intr) intr = (const float*)d_in[n_in - 1];

    prep_kernel<<<NV, NG>>>(xyz, feats, scal, rot, opac, C2W, intr);
    dim3 grid(64, NV);
    render_kernel<<<grid, 256>>>((float*)d_out);
}